// round 1
// baseline (speedup 1.0000x reference)
#include <cuda_runtime.h>
#include <cuda_bf16.h>

// ---------------- problem constants ----------------
#define Bq   8
#define Sq   1024
#define Dq   512
#define Hq   8
#define KDq  512
#define DMq  4096          // H*KD
#define FFq  2048
#define NTOK (Bq*Sq)       // 8192
#define LN_EPS 1e-3f

// ---------------- scratch (device globals; no allocation allowed) ----------
__device__ float g_Q  [(long long)NTOK * DMq];     // 128 MB
__device__ float g_K  [(long long)NTOK * DMq];     // 128 MB
__device__ float g_V  [(long long)NTOK * DMq];     // 128 MB
__device__ float g_S  [(long long)Bq * Hq * Sq * Sq]; // 256 MB scores/attn
__device__ float g_CTX[(long long)NTOK * DMq];     // 128 MB
__device__ float g_AO [(long long)NTOK * Dq];      // 16 MB
__device__ float g_X1 [(long long)NTOK * Dq];      // 16 MB
__device__ float g_F1 [(long long)NTOK * FFq];     // 64 MB
__device__ float g_F2 [(long long)NTOK * Dq];      // 16 MB

// ---------------- generic 128x128x16 SGEMM -----------------
// C = alpha * A @ B (+bias) (+relu). TB => B is [N,K] row-major (C = A @ B^T).
// Batched via blockIdx.z with split offsets: zo = z/hdiv, zi = z%hdiv.
template<bool TB, bool RELU>
__global__ void __launch_bounds__(256)
gemm128(const float* __restrict__ A, const float* __restrict__ B,
        float* __restrict__ C, const float* __restrict__ bias,
        int K, int lda, int ldb, int ldc, int hdiv,
        long long sAo, long long sAi, long long sBo, long long sBi,
        long long sCo, long long sCi, float alpha)
{
    __shared__ float As[16][132];
    __shared__ float Bs[16][132];

    const int z  = blockIdx.z;
    const int zo = z / hdiv;
    const int zi = z - zo * hdiv;
    const float* Ab = A + zo * sAo + (long long)zi * sAi;
    const float* Bb = B + zo * sBo + (long long)zi * sBi;
    float*       Cb = C + zo * sCo + (long long)zi * sCi;

    const int bm = blockIdx.y * 128;
    const int bn = blockIdx.x * 128;
    const int tid = threadIdx.x;
    const int tx = tid & 15;        // 0..15
    const int ty = tid >> 4;        // 0..15

    // A-tile (and TB B-tile) load mapping: 64 rows x 4 float4 per pass
    const int arow = tid >> 2;              // 0..63
    const int acol = (tid & 3) << 2;        // 0,4,8,12
    // NN B-tile load mapping: 8 k-rows x 32 float4 per pass
    const int brow = tid >> 5;              // 0..7
    const int bcol = (tid & 31) << 2;       // 0..124

    float acc[8][8];
    #pragma unroll
    for (int i = 0; i < 8; i++)
        #pragma unroll
        for (int j = 0; j < 8; j++) acc[i][j] = 0.f;

    for (int k0 = 0; k0 < K; k0 += 16) {
        // ---- load A tile (transposed into As[k][m]) ----
        #pragma unroll
        for (int it = 0; it < 2; it++) {
            int r = arow + it * 64;
            float4 v = *(const float4*)&Ab[(long long)(bm + r) * lda + k0 + acol];
            As[acol + 0][r] = v.x; As[acol + 1][r] = v.y;
            As[acol + 2][r] = v.z; As[acol + 3][r] = v.w;
        }
        // ---- load B tile ----
        if (TB) {
            #pragma unroll
            for (int it = 0; it < 2; it++) {
                int r = arow + it * 64;
                float4 v = *(const float4*)&Bb[(long long)(bn + r) * ldb + k0 + acol];
                Bs[acol + 0][r] = v.x; Bs[acol + 1][r] = v.y;
                Bs[acol + 2][r] = v.z; Bs[acol + 3][r] = v.w;
            }
        } else {
            #pragma unroll
            for (int it = 0; it < 2; it++) {
                int r = brow + it * 8;
                float4 v = *(const float4*)&Bb[(long long)(k0 + r) * ldb + bn + bcol];
                *(float4*)&Bs[r][bcol] = v;
            }
        }
        __syncthreads();

        #pragma unroll
        for (int kk = 0; kk < 16; kk++) {
            float a[8], b[8];
            *(float4*)(a)     = *(const float4*)&As[kk][ty * 8];
            *(float4*)(a + 4) = *(const float4*)&As[kk][ty * 8 + 4];
            *(float4*)(b)     = *(const float4*)&Bs[kk][tx * 8];
            *(float4*)(b + 4) = *(const float4*)&Bs[kk][tx * 8 + 4];
            #pragma unroll
            for (int i = 0; i < 8; i++)
                #pragma unroll
                for (int j = 0; j < 8; j++)
                    acc[i][j] += a[i] * b[j];
        }
        __syncthreads();
    }

    // ---- epilogue: scale, bias, relu, store ----
    #pragma unroll
    for (int i = 0; i < 8; i++) {
        long long row = bm + ty * 8 + i;
        #pragma unroll
        for (int jj = 0; jj < 2; jj++) {
            int col = bn + tx * 8 + jj * 4;
            float4 v;
            v.x = acc[i][jj * 4 + 0] * alpha;
            v.y = acc[i][jj * 4 + 1] * alpha;
            v.z = acc[i][jj * 4 + 2] * alpha;
            v.w = acc[i][jj * 4 + 3] * alpha;
            if (bias) {
                float4 bvv = *(const float4*)&bias[col];
                v.x += bvv.x; v.y += bvv.y; v.z += bvv.z; v.w += bvv.w;
            }
            if (RELU) {
                v.x = fmaxf(v.x, 0.f); v.y = fmaxf(v.y, 0.f);
                v.z = fmaxf(v.z, 0.f); v.w = fmaxf(v.w, 0.f);
            }
            *(float4*)&Cb[row * ldc + col] = v;
        }
    }
}

// ---------------- row softmax over 1024 elements -------------
__global__ void __launch_bounds__(256)
softmax1024(float* __restrict__ data)
{
    __shared__ float sh[8];
    long long row = blockIdx.x;
    float* p = data + row * 1024;
    int tid = threadIdx.x;
    float4 v = ((float4*)p)[tid];

    float m = fmaxf(fmaxf(v.x, v.y), fmaxf(v.z, v.w));
    #pragma unroll
    for (int o = 16; o; o >>= 1) m = fmaxf(m, __shfl_xor_sync(0xffffffffu, m, o));
    if ((tid & 31) == 0) sh[tid >> 5] = m;
    __syncthreads();
    if (tid == 0) {
        float t = sh[0];
        #pragma unroll
        for (int i = 1; i < 8; i++) t = fmaxf(t, sh[i]);
        sh[0] = t;
    }
    __syncthreads();
    m = sh[0];
    __syncthreads();   // protect sh before reuse

    v.x = __expf(v.x - m); v.y = __expf(v.y - m);
    v.z = __expf(v.z - m); v.w = __expf(v.w - m);
    float s = v.x + v.y + v.z + v.w;
    #pragma unroll
    for (int o = 16; o; o >>= 1) s += __shfl_xor_sync(0xffffffffu, s, o);
    if ((tid & 31) == 0) sh[tid >> 5] = s;
    __syncthreads();
    if (tid == 0) {
        float t = 0.f;
        #pragma unroll
        for (int i = 0; i < 8; i++) t += sh[i];
        sh[0] = 1.0f / t;
    }
    __syncthreads();
    float inv = sh[0];
    v.x *= inv; v.y *= inv; v.z *= inv; v.w *= inv;
    ((float4*)p)[tid] = v;
}

// ---------------- residual add + LayerNorm (D=512) -----------
__global__ void __launch_bounds__(128)
add_ln512(const float* __restrict__ A, const float* __restrict__ Bi,
          float* __restrict__ O, const float* __restrict__ g,
          const float* __restrict__ be)
{
    __shared__ float shs[4], shq[4];
    __shared__ float mu_s, rs_s;
    long long row = blockIdx.x;
    int tid = threadIdx.x;   // 128 threads, 4 elems each

    float4 x = ((const float4*)(A + row * 512))[tid];
    float4 y = ((const float4*)(Bi + row * 512))[tid];
    x.x += y.x; x.y += y.y; x.z += y.z; x.w += y.w;

    float s = x.x + x.y + x.z + x.w;
    float q = x.x * x.x + x.y * x.y + x.z * x.z + x.w * x.w;
    #pragma unroll
    for (int o = 16; o; o >>= 1) {
        s += __shfl_xor_sync(0xffffffffu, s, o);
        q += __shfl_xor_sync(0xffffffffu, q, o);
    }
    if ((tid & 31) == 0) { shs[tid >> 5] = s; shq[tid >> 5] = q; }
    __syncthreads();
    if (tid == 0) {
        float ts = shs[0] + shs[1] + shs[2] + shs[3];
        float tq = shq[0] + shq[1] + shq[2] + shq[3];
        float mu = ts * (1.0f / 512.0f);
        float var = tq * (1.0f / 512.0f) - mu * mu;
        mu_s = mu;
        rs_s = rsqrtf(var + LN_EPS);
    }
    __syncthreads();
    float mu = mu_s, r = rs_s;

    float4 gv = ((const float4*)g)[tid];
    float4 bv = ((const float4*)be)[tid];
    float4 o4;
    o4.x = (x.x - mu) * r * gv.x + bv.x;
    o4.y = (x.y - mu) * r * gv.y + bv.y;
    o4.z = (x.z - mu) * r * gv.z + bv.z;
    o4.w = (x.w - mu) * r * gv.w + bv.w;
    ((float4*)(O + row * 512))[tid] = o4;
}

// ---------------- launch ----------------
extern "C" void kernel_launch(void* const* d_in, const int* in_sizes, int n_in,
                              void* d_out, int out_size)
{
    const float* X   = (const float*)d_in[0];
    const float* Wq  = (const float*)d_in[1];  const float* bq = (const float*)d_in[2];
    const float* Wk  = (const float*)d_in[3];  const float* bk = (const float*)d_in[4];
    const float* Wv  = (const float*)d_in[5];  const float* bv = (const float*)d_in[6];
    const float* Wo  = (const float*)d_in[7];  const float* bo = (const float*)d_in[8];
    const float* W1  = (const float*)d_in[9];  const float* b1 = (const float*)d_in[10];
    const float* W2  = (const float*)d_in[11]; const float* b2 = (const float*)d_in[12];
    const float* g1  = (const float*)d_in[13]; const float* be1 = (const float*)d_in[14];
    const float* g2  = (const float*)d_in[15]; const float* be2 = (const float*)d_in[16];
    float* OUT = (float*)d_out;

    float *Q, *Km, *V, *S, *CTX, *AO, *X1, *F1, *F2;
    cudaGetSymbolAddress((void**)&Q,  g_Q);
    cudaGetSymbolAddress((void**)&Km, g_K);
    cudaGetSymbolAddress((void**)&V,  g_V);
    cudaGetSymbolAddress((void**)&S,  g_S);
    cudaGetSymbolAddress((void**)&CTX,g_CTX);
    cudaGetSymbolAddress((void**)&AO, g_AO);
    cudaGetSymbolAddress((void**)&X1, g_X1);
    cudaGetSymbolAddress((void**)&F1, g_F1);
    cudaGetSymbolAddress((void**)&F2, g_F2);

    const dim3 T(256);
    const long long SDM = (long long)Sq * DMq;       // per-batch stride of Q/K/V/ctx
    const long long SS  = (long long)Sq * Sq;        // per-head stride of scores
    const float scl = 0.044194173824159216f;         // 1/sqrt(512)

    // 1-3) Q,K,V projections: [8192,512] @ [512,4096] + bias
    gemm128<false,false><<<dim3(32,64,1), T>>>(X, Wq, Q,  bq, 512, Dq, DMq, DMq, 1, 0,0,0,0,0,0, 1.f);
    gemm128<false,false><<<dim3(32,64,1), T>>>(X, Wk, Km, bk, 512, Dq, DMq, DMq, 1, 0,0,0,0,0,0, 1.f);
    gemm128<false,false><<<dim3(32,64,1), T>>>(X, Wv, V,  bv, 512, Dq, DMq, DMq, 1, 0,0,0,0,0,0, 1.f);

    // 4) scores[b,h] = Q_bh @ K_bh^T / sqrt(512)   (64 batched NT GEMMs 1024x1024x512)
    gemm128<true,false><<<dim3(8,8,64), T>>>(Q, Km, S, nullptr, 512,
        DMq, DMq, Sq, Hq,
        SDM, KDq,  SDM, KDq,  (long long)Hq*SS, SS, scl);

    // 5) softmax over rows
    softmax1024<<<Bq*Hq*Sq, 256>>>(S);

    // 6) ctx[b,h] = attn @ V_bh   (64 batched NN GEMMs 1024x512x1024)
    gemm128<false,false><<<dim3(4,8,64), T>>>(S, V, CTX, nullptr, 1024,
        Sq, DMq, DMq, Hq,
        (long long)Hq*SS, SS,  SDM, KDq,  SDM, KDq, 1.f);

    // 7) attn_out = ctx @ Wo + bo : [8192,4096]@[4096,512]
    gemm128<false,false><<<dim3(4,64,1), T>>>(CTX, Wo, AO, bo, 4096, DMq, Dq, Dq, 1, 0,0,0,0,0,0, 1.f);

    // 8) x1 = LN(inputs + attn_out)
    add_ln512<<<NTOK, 128>>>(X, AO, X1, g1, be1);

    // 9) ffn1 = relu(x1 @ W1 + b1): [8192,512]@[512,2048]
    gemm128<false,true ><<<dim3(16,64,1), T>>>(X1, W1, F1, b1, 512, Dq, FFq, FFq, 1, 0,0,0,0,0,0, 1.f);

    // 10) ffn2 = ffn1 @ W2 + b2: [8192,2048]@[2048,512]
    gemm128<false,false><<<dim3(4,64,1), T>>>(F1, W2, F2, b2, 2048, FFq, Dq, Dq, 1, 0,0,0,0,0,0, 1.f);

    // 11) out = LN(x1 + ffn2)
    add_ln512<<<NTOK, 128>>>(X1, F2, OUT, g2, be2);
}